// round 5
// baseline (speedup 1.0000x reference)
#include <cuda_runtime.h>
#include <cuda_fp16.h>
#include <cstdint>

// Problem: B=2, S=4096, HS=4096, H=32, KV=8, D=128 -> M = 8192
#define M_TOK   8192
#define HS_DIM  4096
#define KVD_DIM 1024
#define N_HEADS 32
#define N_KV    8
#define HEAD_D  128

// GEMM tiling (fp16 mma.sync, fp32 accum)
#define BM 128
#define BN 256
#define BK 64            // 64 halfs = 128 B rows
#define STAGES 4
#define GT 256           // 8 warps: 2 (m) x 4 (n), warp tile 64x64
#define STAGE_A 16384    // 128 x 64 halfs
#define STAGE_B 32768    // 256 x 64 halfs
#define SMEM_BYTES (STAGES * (STAGE_A + STAGE_B) + 256)

// Scratch (__device__ globals: allocation-free per harness rules)
__device__ float  g_q  [(size_t)M_TOK * HS_DIM];
__device__ float  g_k  [(size_t)M_TOK * KVD_DIM];
__device__ float  g_v  [(size_t)M_TOK * KVD_DIM];
__device__ __align__(16) __half g_xh  [(size_t)M_TOK * HS_DIM];
__device__ __align__(16) __half g_aoh [(size_t)M_TOK * HS_DIM];
__device__ __align__(16) __half g_WqTh[(size_t)HS_DIM * HS_DIM];    // [N,K] K-major
__device__ __align__(16) __half g_WkTh[(size_t)KVD_DIM * HS_DIM];
__device__ __align__(16) __half g_WvTh[(size_t)KVD_DIM * HS_DIM];
__device__ __align__(16) __half g_WoTh[(size_t)HS_DIM * HS_DIM];

// ---------------------------------------------------------------------------
// PTX helpers (sm_80-era only: valid on plain sm_103 target)
// ---------------------------------------------------------------------------
__device__ __forceinline__ uint32_t smem_u32(const void* p) {
    uint32_t a;
    asm("{ .reg .u64 t; cvta.to.shared.u64 t, %1; cvt.u32.u64 %0, t; }" : "=r"(a) : "l"(p));
    return a;
}
#define CP_ASYNC16(smem, gptr) \
    asm volatile("cp.async.cg.shared.global [%0], [%1], 16;\n" :: "r"(smem), "l"(gptr))
#define CP_COMMIT() asm volatile("cp.async.commit_group;\n" ::: "memory")
#define CP_WAIT(n)  asm volatile("cp.async.wait_group %0;\n" :: "n"(n) : "memory")

#define LDSM_X4(r, addr) \
    asm volatile("ldmatrix.sync.aligned.m8n8.x4.shared.b16 {%0,%1,%2,%3}, [%4];" \
        : "=r"((r)[0]), "=r"((r)[1]), "=r"((r)[2]), "=r"((r)[3]) : "r"(addr))

#define MMA16816(d, a, b0, b1) \
    asm volatile("mma.sync.aligned.m16n8k16.row.col.f32.f16.f16.f32 " \
        "{%0,%1,%2,%3}, {%4,%5,%6,%7}, {%8,%9}, {%0,%1,%2,%3};" \
        : "+f"((d)[0]), "+f"((d)[1]), "+f"((d)[2]), "+f"((d)[3]) \
        : "r"((a)[0]), "r"((a)[1]), "r"((a)[2]), "r"((a)[3]), "r"(b0), "r"(b1))

// ---------------------------------------------------------------------------
// fp16 GEMM: C[M,N](f32) = A[M,K](f16, row-major) @ Bt[N,K](f16, K-major)^T
// Grid (N/BN, M/BM), 256 threads, 4-stage cp.async pipeline, ldmatrix + mma.
// CTA tile 128x256, warp tile 64x64 (acc = 128 fp32 regs/thread).
// ---------------------------------------------------------------------------
__global__ __launch_bounds__(GT, 1)
void gemm_f16(const __half* __restrict__ A, const __half* __restrict__ Bt,
              float* __restrict__ C, int K, int N)
{
    extern __shared__ char smem_raw[];
    const uint32_t base = (smem_u32(smem_raw) + 127u) & ~127u;
    const uint32_t sA = base;
    const uint32_t sB = base + STAGES * STAGE_A;

    const int tid  = threadIdx.x;
    const int wid  = tid >> 5, lane = tid & 31;
    const int mtile = blockIdx.y, ntile = blockIdx.x;
    const int warp_m = wid & 1;        // 2 m-warps (64 rows each)
    const int warp_n = wid >> 1;       // 4 n-warps (64 cols each)

    const __half* Ag = A  + (size_t)(mtile * BM) * K;
    const __half* Bg = Bt + (size_t)(ntile * BN) * K;

    float acc[4][8][4];
    #pragma unroll
    for (int i = 0; i < 4; i++)
        #pragma unroll
        for (int j = 0; j < 8; j++)
            #pragma unroll
            for (int r = 0; r < 4; r++) acc[i][j][r] = 0.f;

    // Stage loader: A 1024 chunks (4/thread), B 2048 chunks (8/thread);
    // 128B rows, XOR-16B swizzle for conflict-free ldmatrix.
    auto load_stage = [&](int s, int k0) {
        uint32_t a0 = sA + s * STAGE_A, b0 = sB + s * STAGE_B;
        #pragma unroll
        for (int j = 0; j < 4; j++) {
            int c = tid + j * 256;
            int r = c >> 3, c16 = c & 7;
            uint32_t so = a0 + ((r * 128 + c16 * 16) ^ ((r & 7) << 4));
            CP_ASYNC16(so, Ag + (size_t)r * K + k0 + c16 * 8);
        }
        #pragma unroll
        for (int j = 0; j < 8; j++) {
            int c = tid + j * 256;
            int r = c >> 3, c16 = c & 7;
            uint32_t so = b0 + ((r * 128 + c16 * 16) ^ ((r & 7) << 4));
            CP_ASYNC16(so, Bg + (size_t)r * K + k0 + c16 * 8);
        }
        CP_COMMIT();
    };

    const int NIT = K / BK;
    load_stage(0, 0); load_stage(1, BK); load_stage(2, 2 * BK);

    for (int i = 0; i < NIT; i++) {
        const int s = i & 3;
        CP_WAIT(2);                    // stage i landed
        __syncthreads();               // also protects buffer (i+3)&3 for reuse
        if (i + 3 < NIT) load_stage((i + 3) & 3, (i + 3) * BK);

        const uint32_t aB = sA + s * STAGE_A;
        const uint32_t bB = sB + s * STAGE_B;
        #pragma unroll
        for (int ks = 0; ks < 4; ks++) {
            const int kbyte = ks * 32;                    // k16 = 32 bytes
            uint32_t a[4][4], bb[4][4];
            #pragma unroll
            for (int ii = 0; ii < 4; ii++) {              // A: 4 x (m16,k16)
                int row = warp_m * 64 + ii * 16 + (lane & 15);
                uint32_t ad = aB + ((row * 128 + kbyte + ((lane >> 4) << 4)) ^ ((row & 7) << 4));
                LDSM_X4(a[ii], ad);
            }
            #pragma unroll
            for (int jj = 0; jj < 4; jj++) {              // B: 4 x (n16,k16)
                int row = warp_n * 64 + jj * 16 + (lane & 15);
                uint32_t bd = bB + ((row * 128 + kbyte + ((lane >> 4) << 4)) ^ ((row & 7) << 4));
                LDSM_X4(bb[jj], bd);
            }
            #pragma unroll
            for (int ii = 0; ii < 4; ii++)
                #pragma unroll
                for (int j = 0; j < 8; j++)
                    MMA16816(acc[ii][j], a[ii], bb[j >> 1][j & 1], bb[j >> 1][2 + (j & 1)]);
        }
    }

    // Epilogue
    float* Cp = C + (size_t)(mtile * BM) * N + ntile * BN;
    #pragma unroll
    for (int ii = 0; ii < 4; ii++)
        #pragma unroll
        for (int j = 0; j < 8; j++) {
            int r0 = warp_m * 64 + ii * 16 + (lane >> 2);
            int c0 = warp_n * 64 + j * 8 + (lane & 3) * 2;
            float2 v0 = { acc[ii][j][0], acc[ii][j][1] };
            float2 v1 = { acc[ii][j][2], acc[ii][j][3] };
            *(float2*)(Cp + (size_t)r0 * N + c0)       = v0;
            *(float2*)(Cp + (size_t)(r0 + 8) * N + c0) = v1;
        }
}

// ---------------------------------------------------------------------------
// Elementwise fp32 -> fp16 (rn). 4 elems/thread.
// ---------------------------------------------------------------------------
__global__ __launch_bounds__(256)
void f32_to_f16(const float* __restrict__ in, __half* __restrict__ out)
{
    size_t i = (size_t)blockIdx.x * blockDim.x + threadIdx.x;
    float4 v = ((const float4*)in)[i];
    __half2* o = (__half2*)out;
    o[2 * i + 0] = __floats2half2_rn(v.x, v.y);
    o[2 * i + 1] = __floats2half2_rn(v.z, v.w);
}

// ---------------------------------------------------------------------------
// Transpose [R,C] f32 -> [C,R] f16 (rn)
// ---------------------------------------------------------------------------
__global__ __launch_bounds__(256)
void transpose_f16(const float* __restrict__ in, __half* __restrict__ out, int R, int C)
{
    __shared__ float t[32][33];
    const int tx = threadIdx.x, ty = threadIdx.y;     // 32 x 8
    const int bx = blockIdx.x * 32, by = blockIdx.y * 32;
    #pragma unroll
    for (int r = 0; r < 32; r += 8)
        t[ty + r][tx] = in[(size_t)(by + ty + r) * C + bx + tx];
    __syncthreads();
    #pragma unroll
    for (int r = 0; r < 32; r += 8)
        out[(size_t)(bx + ty + r) * R + by + tx] = __float2half_rn(t[tx][ty + r]);
}

// ---------------------------------------------------------------------------
// Per-token attention (RoPE cancels exactly in q.k; GQA repeat collapses).
// Writes ao directly as fp16 (feeds the output GEMM).
// ---------------------------------------------------------------------------
__global__ __launch_bounds__(128)
void attn_kernel(const float* __restrict__ q, const float* __restrict__ k,
                 const float* __restrict__ v, __half* __restrict__ ao)
{
    const int tok = blockIdx.x;
    const int tid = threadIdx.x;

    __shared__ float qs[N_HEADS][132];
    __shared__ float ks[N_KV][132];
    __shared__ float vs[N_KV][132];
    __shared__ float sc[N_HEADS][8];
    __shared__ float w [N_HEADS][8];

    const float* qg = q + (size_t)tok * HS_DIM;
    const float* kg = k + (size_t)tok * KVD_DIM;
    const float* vg = v + (size_t)tok * KVD_DIM;

    for (int i = tid; i < HS_DIM / 4; i += 128) {
        float4 t4 = *(const float4*)(qg + i * 4);
        int h = (i * 4) >> 7, d = (i * 4) & 127;
        *(float4*)&qs[h][d] = t4;
    }
    for (int i = tid; i < KVD_DIM / 4; i += 128) {
        float4 t4 = *(const float4*)(kg + i * 4);
        int g = (i * 4) >> 7, d = (i * 4) & 127;
        *(float4*)&ks[g][d] = t4;
    }
    for (int i = tid; i < KVD_DIM / 4; i += 128) {
        float4 t4 = *(const float4*)(vg + i * 4);
        int g = (i * 4) >> 7, d = (i * 4) & 127;
        *(float4*)&vs[g][d] = t4;
    }
    __syncthreads();

    const float scale = 0.088388347648318447f;   // 1/sqrt(128)
    #pragma unroll
    for (int r = 0; r < 2; r++) {
        int sid = r * 128 + tid;
        int h = sid >> 3, g = sid & 7;
        float a = 0.f;
        #pragma unroll 8
        for (int d = 0; d < HEAD_D; d++) a += qs[h][d] * ks[g][d];
        sc[h][g] = a * scale;
    }
    __syncthreads();

    if (tid < N_HEADS) {
        float m = sc[tid][0];
        #pragma unroll
        for (int g = 1; g < 8; g++) m = fmaxf(m, sc[tid][g]);
        float e[8], s = 0.f;
        #pragma unroll
        for (int g = 0; g < 8; g++) { e[g] = __expf(sc[tid][g] - m); s += e[g]; }
        float inv = 1.f / s;
        #pragma unroll
        for (int g = 0; g < 8; g++) w[tid][g] = e[g] * inv;
    }
    __syncthreads();

    float vr[8];
    #pragma unroll
    for (int g = 0; g < 8; g++) vr[g] = vs[g][tid];
    __half* og = ao + (size_t)tok * HS_DIM;
    #pragma unroll
    for (int h = 0; h < N_HEADS; h++) {
        float a = 0.f;
        #pragma unroll
        for (int g = 0; g < 8; g++) a += w[h][g] * vr[g];
        og[h * HEAD_D + tid] = __float2half_rn(a);
    }
}

// ---------------------------------------------------------------------------
extern "C" void kernel_launch(void* const* d_in, const int* in_sizes, int n_in,
                              void* d_out, int out_size)
{
    const float* x  = (const float*)d_in[0];
    const float* Wq = (const float*)d_in[1];
    const float* Wk = (const float*)d_in[2];
    const float* Wv = (const float*)d_in[3];
    const float* Wo = (const float*)d_in[4];
    float* out = (float*)d_out;

    float *q, *k, *v;
    __half *xh, *aoh, *WqTh, *WkTh, *WvTh, *WoTh;
    cudaGetSymbolAddress((void**)&q,    g_q);
    cudaGetSymbolAddress((void**)&k,    g_k);
    cudaGetSymbolAddress((void**)&v,    g_v);
    cudaGetSymbolAddress((void**)&xh,   g_xh);
    cudaGetSymbolAddress((void**)&aoh,  g_aoh);
    cudaGetSymbolAddress((void**)&WqTh, g_WqTh);
    cudaGetSymbolAddress((void**)&WkTh, g_WkTh);
    cudaGetSymbolAddress((void**)&WvTh, g_WvTh);
    cudaGetSymbolAddress((void**)&WoTh, g_WoTh);

    cudaFuncSetAttribute(gemm_f16, cudaFuncAttributeMaxDynamicSharedMemorySize, SMEM_BYTES);

    // fp32 -> fp16 input + weight prep
    f32_to_f16<<<(size_t)M_TOK * HS_DIM / 1024, 256>>>(x, xh);
    dim3 tb(32, 8);
    transpose_f16<<<dim3(HS_DIM  / 32, HS_DIM / 32), tb>>>(Wq, WqTh, HS_DIM, HS_DIM);
    transpose_f16<<<dim3(KVD_DIM / 32, HS_DIM / 32), tb>>>(Wk, WkTh, HS_DIM, KVD_DIM);
    transpose_f16<<<dim3(KVD_DIM / 32, HS_DIM / 32), tb>>>(Wv, WvTh, HS_DIM, KVD_DIM);
    transpose_f16<<<dim3(HS_DIM  / 32, HS_DIM / 32), tb>>>(Wo, WoTh, HS_DIM, HS_DIM);

    // Projections (tensor cores via mma.sync)
    gemm_f16<<<dim3(HS_DIM  / BN, M_TOK / BM), GT, SMEM_BYTES>>>(xh, WqTh, q, HS_DIM, HS_DIM);
    gemm_f16<<<dim3(KVD_DIM / BN, M_TOK / BM), GT, SMEM_BYTES>>>(xh, WkTh, k, HS_DIM, KVD_DIM);
    gemm_f16<<<dim3(KVD_DIM / BN, M_TOK / BM), GT, SMEM_BYTES>>>(xh, WvTh, v, HS_DIM, KVD_DIM);

    // Per-token head attention (fp32 in, fp16 out)
    attn_kernel<<<M_TOK, 128>>>(q, k, v, aoh);

    // Output projection
    gemm_f16<<<dim3(HS_DIM / BN, M_TOK / BM), GT, SMEM_BYTES>>>(aoh, WoTh, out, HS_DIM, HS_DIM);
}

// round 11
// speedup vs baseline: 1.4368x; 1.4368x over previous
#include <cuda_runtime.h>
#include <cuda_fp16.h>
#include <cstdint>

// Problem: B=2, S=4096, HS=4096, H=32, KV=8, D=128 -> M = 8192
#define M_TOK   8192
#define HS_DIM  4096
#define KVD_DIM 1024
#define N_HEADS 32
#define N_KV    8
#define HEAD_D  128

// GEMM tiling (fp16 mma.sync, fp32 accum)
// CTA tile 128x128, warp tile 64x32 (8 warps: 2m x 4n), BK=32, 4 stages.
// 64 KB smem/CTA + <=128 regs/thread -> 2 CTAs/SM (16 warps) to hide
// the per-iteration CP_WAIT+syncthreads bubble.
#define BM 128
#define BN 128
#define BK 32            // 32 halfs = 64 B rows (SW64-style swizzle)
#define STAGES 4
#define GT 256
#define STAGE_A 8192     // 128 x 32 halfs
#define STAGE_B 8192
#define SMEM_BYTES (STAGES * (STAGE_A + STAGE_B) + 256)

// Scratch (__device__ globals: allocation-free per harness rules)
__device__ float  g_q  [(size_t)M_TOK * HS_DIM];
__device__ float  g_k  [(size_t)M_TOK * KVD_DIM];
__device__ float  g_v  [(size_t)M_TOK * KVD_DIM];
__device__ __align__(16) __half g_xh  [(size_t)M_TOK * HS_DIM];
__device__ __align__(16) __half g_aoh [(size_t)M_TOK * HS_DIM];
__device__ __align__(16) __half g_WqTh[(size_t)HS_DIM * HS_DIM];    // [N,K] K-major
__device__ __align__(16) __half g_WkTh[(size_t)KVD_DIM * HS_DIM];
__device__ __align__(16) __half g_WvTh[(size_t)KVD_DIM * HS_DIM];
__device__ __align__(16) __half g_WoTh[(size_t)HS_DIM * HS_DIM];

// ---------------------------------------------------------------------------
// PTX helpers (sm_80-era only: valid on plain sm_103 target)
// ---------------------------------------------------------------------------
__device__ __forceinline__ uint32_t smem_u32(const void* p) {
    uint32_t a;
    asm("{ .reg .u64 t; cvta.to.shared.u64 t, %1; cvt.u32.u64 %0, t; }" : "=r"(a) : "l"(p));
    return a;
}
#define CP_ASYNC16(smem, gptr) \
    asm volatile("cp.async.cg.shared.global [%0], [%1], 16;\n" :: "r"(smem), "l"(gptr))
#define CP_COMMIT() asm volatile("cp.async.commit_group;\n" ::: "memory")
#define CP_WAIT(n)  asm volatile("cp.async.wait_group %0;\n" :: "n"(n) : "memory")

#define LDSM_X4(r, addr) \
    asm volatile("ldmatrix.sync.aligned.m8n8.x4.shared.b16 {%0,%1,%2,%3}, [%4];" \
        : "=r"((r)[0]), "=r"((r)[1]), "=r"((r)[2]), "=r"((r)[3]) : "r"(addr))

#define MMA16816(d, a, b0, b1) \
    asm volatile("mma.sync.aligned.m16n8k16.row.col.f32.f16.f16.f32 " \
        "{%0,%1,%2,%3}, {%4,%5,%6,%7}, {%8,%9}, {%0,%1,%2,%3};" \
        : "+f"((d)[0]), "+f"((d)[1]), "+f"((d)[2]), "+f"((d)[3]) \
        : "r"((a)[0]), "r"((a)[1]), "r"((a)[2]), "r"((a)[3]), "r"(b0), "r"(b1))

// SW64 swizzle for 64B rows, 16B granules: off ^ ((row & 6) << 3)
__device__ __forceinline__ uint32_t sw64(int row, int colbyte) {
    return (uint32_t)((row * 64 + colbyte) ^ ((row & 6) << 3));
}

// ---------------------------------------------------------------------------
// fp16 GEMM: C[M,N](f32) = A[M,K](f16, row-major) @ Bt[N,K](f16, K-major)^T
// Grid (N/BN, M/BM), 256 threads, 4-stage cp.async pipeline, ldmatrix + mma.
// ---------------------------------------------------------------------------
__global__ __launch_bounds__(GT, 2)
void gemm_f16(const __half* __restrict__ A, const __half* __restrict__ Bt,
              float* __restrict__ C, int K, int N)
{
    extern __shared__ char smem_raw[];
    const uint32_t base = (smem_u32(smem_raw) + 127u) & ~127u;
    const uint32_t sA = base;
    const uint32_t sB = base + STAGES * STAGE_A;

    const int tid  = threadIdx.x;
    const int wid  = tid >> 5, lane = tid & 31;
    const int mtile = blockIdx.y, ntile = blockIdx.x;
    const int warp_m = wid & 1;        // 2 m-warps (64 rows each)
    const int warp_n = wid >> 1;       // 4 n-warps (32 cols each)

    const __half* Ag = A  + (size_t)(mtile * BM) * K;
    const __half* Bg = Bt + (size_t)(ntile * BN) * K;

    float acc[4][4][4];
    #pragma unroll
    for (int i = 0; i < 4; i++)
        #pragma unroll
        for (int j = 0; j < 4; j++)
            #pragma unroll
            for (int r = 0; r < 4; r++) acc[i][j][r] = 0.f;

    // Stage loader: A and B each 512 16B-chunks -> 2 chunks/thread each.
    // chunk c -> row = c>>2, col16 = c&3 (64B rows).
    auto load_stage = [&](int s, int k0) {
        uint32_t a0 = sA + s * STAGE_A, b0 = sB + s * STAGE_B;
        #pragma unroll
        for (int j = 0; j < 2; j++) {
            int c = tid + j * 256;
            int r = c >> 2, c16 = c & 3;
            CP_ASYNC16(a0 + sw64(r, c16 * 16), Ag + (size_t)r * K + k0 + c16 * 8);
        }
        #pragma unroll
        for (int j = 0; j < 2; j++) {
            int c = tid + j * 256;
            int r = c >> 2, c16 = c & 3;
            CP_ASYNC16(b0 + sw64(r, c16 * 16), Bg + (size_t)r * K + k0 + c16 * 8);
        }
        CP_COMMIT();
    };

    const int NIT = K / BK;
    load_stage(0, 0); load_stage(1, BK); load_stage(2, 2 * BK);

    for (int i = 0; i < NIT; i++) {
        const int s = i & 3;
        CP_WAIT(2);                    // stage i landed
        __syncthreads();               // all warps done with buffer (i+3)&3
        if (i + 3 < NIT) load_stage((i + 3) & 3, (i + 3) * BK);

        const uint32_t aB = sA + s * STAGE_A;
        const uint32_t bB = sB + s * STAGE_B;
        #pragma unroll
        for (int ks = 0; ks < 2; ks++) {
            const int kbyte = ks * 32 + ((lane >> 4) << 4);   // k16 = 32 bytes
            uint32_t a[4][4], bb[2][4];
            #pragma unroll
            for (int ii = 0; ii < 4; ii++) {                  // A: 4 x (m16,k16)
                int row = warp_m * 64 + ii * 16 + (lane & 15);
                LDSM_X4(a[ii], aB + sw64(row, kbyte));
            }
            #pragma unroll
            for (int jj = 0; jj < 2; jj++) {                  // B: 2 x (n16,k16)
                int row = warp_n * 32 + jj * 16 + (lane & 15);
                LDSM_X4(bb[jj], bB + sw64(row, kbyte));
            }
            #pragma unroll
            for (int ii = 0; ii < 4; ii++)
                #pragma unroll
                for (int j = 0; j < 4; j++)
                    MMA16816(acc[ii][j], a[ii], bb[j >> 1][j & 1], bb[j >> 1][2 + (j & 1)]);
        }
    }

    // Epilogue
    float* Cp = C + (size_t)(mtile * BM) * N + ntile * BN;
    #pragma unroll
    for (int ii = 0; ii < 4; ii++)
        #pragma unroll
        for (int j = 0; j < 4; j++) {
            int r0 = warp_m * 64 + ii * 16 + (lane >> 2);
            int c0 = warp_n * 32 + j * 8 + (lane & 3) * 2;
            float2 v0 = { acc[ii][j][0], acc[ii][j][1] };
            float2 v1 = { acc[ii][j][2], acc[ii][j][3] };
            *(float2*)(Cp + (size_t)r0 * N + c0)       = v0;
            *(float2*)(Cp + (size_t)(r0 + 8) * N + c0) = v1;
        }
}

// ---------------------------------------------------------------------------
// Elementwise fp32 -> fp16 (rn). 4 elems/thread.
// ---------------------------------------------------------------------------
__global__ __launch_bounds__(256)
void f32_to_f16(const float* __restrict__ in, __half* __restrict__ out)
{
    size_t i = (size_t)blockIdx.x * blockDim.x + threadIdx.x;
    float4 v = ((const float4*)in)[i];
    __half2* o = (__half2*)out;
    o[2 * i + 0] = __floats2half2_rn(v.x, v.y);
    o[2 * i + 1] = __floats2half2_rn(v.z, v.w);
}

// ---------------------------------------------------------------------------
// Transpose [R,C] f32 -> [C,R] f16 (rn)
// ---------------------------------------------------------------------------
__global__ __launch_bounds__(256)
void transpose_f16(const float* __restrict__ in, __half* __restrict__ out, int R, int C)
{
    __shared__ float t[32][33];
    const int tx = threadIdx.x, ty = threadIdx.y;     // 32 x 8
    const int bx = blockIdx.x * 32, by = blockIdx.y * 32;
    #pragma unroll
    for (int r = 0; r < 32; r += 8)
        t[ty + r][tx] = in[(size_t)(by + ty + r) * C + bx + tx];
    __syncthreads();
    #pragma unroll
    for (int r = 0; r < 32; r += 8)
        out[(size_t)(bx + ty + r) * R + by + tx] = __float2half_rn(t[tx][ty + r]);
}

// ---------------------------------------------------------------------------
// Per-token attention (RoPE cancels exactly in q.k; GQA repeat collapses).
// Writes ao directly as fp16 (feeds the output GEMM).
// ---------------------------------------------------------------------------
__global__ __launch_bounds__(128)
void attn_kernel(const float* __restrict__ q, const float* __restrict__ k,
                 const float* __restrict__ v, __half* __restrict__ ao)
{
    const int tok = blockIdx.x;
    const int tid = threadIdx.x;

    __shared__ float qs[N_HEADS][132];
    __shared__ float ks[N_KV][132];
    __shared__ float vs[N_KV][132];
    __shared__ float sc[N_HEADS][8];
    __shared__ float w [N_HEADS][8];

    const float* qg = q + (size_t)tok * HS_DIM;
    const float* kg = k + (size_t)tok * KVD_DIM;
    const float* vg = v + (size_t)tok * KVD_DIM;

    for (int i = tid; i < HS_DIM / 4; i += 128) {
        float4 t4 = *(const float4*)(qg + i * 4);
        int h = (i * 4) >> 7, d = (i * 4) & 127;
        *(float4*)&qs[h][d] = t4;
    }
    for (int i = tid; i < KVD_DIM / 4; i += 128) {
        float4 t4 = *(const float4*)(kg + i * 4);
        int g = (i * 4) >> 7, d = (i * 4) & 127;
        *(float4*)&ks[g][d] = t4;
    }
    for (int i = tid; i < KVD_DIM / 4; i += 128) {
        float4 t4 = *(const float4*)(vg + i * 4);
        int g = (i * 4) >> 7, d = (i * 4) & 127;
        *(float4*)&vs[g][d] = t4;
    }
    __syncthreads();

    const float scale = 0.088388347648318447f;   // 1/sqrt(128)
    #pragma unroll
    for (int r = 0; r < 2; r++) {
        int sid = r * 128 + tid;
        int h = sid >> 3, g = sid & 7;
        float a = 0.f;
        #pragma unroll 8
        for (int d = 0; d < HEAD_D; d++) a += qs[h][d] * ks[g][d];
        sc[h][g] = a * scale;
    }
    __syncthreads();

    if (tid < N_HEADS) {
        float m = sc[tid][0];
        #pragma unroll
        for (int g = 1; g < 8; g++) m = fmaxf(m, sc[tid][g]);
        float e[8], s = 0.f;
        #pragma unroll
        for (int g = 0; g < 8; g++) { e[g] = __expf(sc[tid][g] - m); s += e[g]; }
        float inv = 1.f / s;
        #pragma unroll
        for (int g = 0; g < 8; g++) w[tid][g] = e[g] * inv;
    }
    __syncthreads();

    float vr[8];
    #pragma unroll
    for (int g = 0; g < 8; g++) vr[g] = vs[g][tid];
    __half* og = ao + (size_t)tok * HS_DIM;
    #pragma unroll
    for (int h = 0; h < N_HEADS; h++) {
        float a = 0.f;
        #pragma unroll
        for (int g = 0; g < 8; g++) a += w[h][g] * vr[g];
        og[h * HEAD_D + tid] = __float2half_rn(a);
    }
}

// ---------------------------------------------------------------------------
extern "C" void kernel_launch(void* const* d_in, const int* in_sizes, int n_in,
                              void* d_out, int out_size)
{
    const float* x  = (const float*)d_in[0];
    const float* Wq = (const float*)d_in[1];
    const float* Wk = (const float*)d_in[2];
    const float* Wv = (const float*)d_in[3];
    const float* Wo = (const float*)d_in[4];
    float* out = (float*)d_out;

    float *q, *k, *v;
    __half *xh, *aoh, *WqTh, *WkTh, *WvTh, *WoTh;
    cudaGetSymbolAddress((void**)&q,    g_q);
    cudaGetSymbolAddress((void**)&k,    g_k);
    cudaGetSymbolAddress((void**)&v,    g_v);
    cudaGetSymbolAddress((void**)&xh,   g_xh);
    cudaGetSymbolAddress((void**)&aoh,  g_aoh);
    cudaGetSymbolAddress((void**)&WqTh, g_WqTh);
    cudaGetSymbolAddress((void**)&WkTh, g_WkTh);
    cudaGetSymbolAddress((void**)&WvTh, g_WvTh);
    cudaGetSymbolAddress((void**)&WoTh, g_WoTh);

    cudaFuncSetAttribute(gemm_f16, cudaFuncAttributeMaxDynamicSharedMemorySize, SMEM_BYTES);

    // fp32 -> fp16 input + weight prep
    f32_to_f16<<<(size_t)M_TOK * HS_DIM / 1024, 256>>>(x, xh);
    dim3 tb(32, 8);
    transpose_f16<<<dim3(HS_DIM  / 32, HS_DIM / 32), tb>>>(Wq, WqTh, HS_DIM, HS_DIM);
    transpose_f16<<<dim3(KVD_DIM / 32, HS_DIM / 32), tb>>>(Wk, WkTh, HS_DIM, KVD_DIM);
    transpose_f16<<<dim3(KVD_DIM / 32, HS_DIM / 32), tb>>>(Wv, WvTh, HS_DIM, KVD_DIM);
    transpose_f16<<<dim3(HS_DIM  / 32, HS_DIM / 32), tb>>>(Wo, WoTh, HS_DIM, HS_DIM);

    // Projections (tensor cores via mma.sync)
    gemm_f16<<<dim3(HS_DIM  / BN, M_TOK / BM), GT, SMEM_BYTES>>>(xh, WqTh, q, HS_DIM, HS_DIM);
    gemm_f16<<<dim3(KVD_DIM / BN, M_TOK / BM), GT, SMEM_BYTES>>>(xh, WkTh, k, HS_DIM, KVD_DIM);
    gemm_f16<<<dim3(KVD_DIM / BN, M_TOK / BM), GT, SMEM_BYTES>>>(xh, WvTh, v, HS_DIM, KVD_DIM);

    // Per-token head attention (fp32 in, fp16 out)
    attn_kernel<<<M_TOK, 128>>>(q, k, v, aoh);

    // Output projection
    gemm_f16<<<dim3(HS_DIM / BN, M_TOK / BM), GT, SMEM_BYTES>>>(aoh, WoTh, out, HS_DIM, HS_DIM);
}

// round 12
// speedup vs baseline: 1.6240x; 1.1303x over previous
#include <cuda_runtime.h>
#include <cuda_fp16.h>
#include <cstdint>

// Problem: B=2, S=4096, HS=4096, H=32, KV=8, D=128 -> M = 8192
#define M_TOK   8192
#define HS_DIM  4096
#define KVD_DIM 1024
#define QKV_DIM 6144     // 4096 (q) + 1024 (k) + 1024 (v)
#define N_HEADS 32
#define N_KV    8
#define HEAD_D  128

// GEMM tiling (fp16 mma.sync, fp32 accum)
// CTA tile 128x128, warp tile 64x32 (8 warps: 2m x 4n), BK=64, 3 stages.
// 96 KB smem/CTA + <=128 regs -> 2 CTAs/SM; 64 iterations (half the syncs of R11).
#define BM 128
#define BN 128
#define BK 64            // 64 halfs = 128 B rows (SW128 swizzle)
#define STAGES 3
#define GT 256
#define STAGE_A 16384    // 128 x 64 halfs
#define STAGE_B 16384
#define SMEM_BYTES (STAGES * (STAGE_A + STAGE_B) + 256)

// Scratch (__device__ globals: allocation-free per harness rules)
__device__ float  g_qkv[(size_t)M_TOK * QKV_DIM];            // packed q|k|v, fp32
__device__ __align__(16) __half g_xh   [(size_t)M_TOK * HS_DIM];
__device__ __align__(16) __half g_aoh  [(size_t)M_TOK * HS_DIM];
__device__ __align__(16) __half g_Wqkv [(size_t)QKV_DIM * HS_DIM];  // [N,K] K-major, q|k|v rows
__device__ __align__(16) __half g_WoTh [(size_t)HS_DIM * HS_DIM];

// ---------------------------------------------------------------------------
// PTX helpers (sm_80-era only: valid on plain sm_103 target)
// ---------------------------------------------------------------------------
__device__ __forceinline__ uint32_t smem_u32(const void* p) {
    uint32_t a;
    asm("{ .reg .u64 t; cvta.to.shared.u64 t, %1; cvt.u32.u64 %0, t; }" : "=r"(a) : "l"(p));
    return a;
}
#define CP_ASYNC16(smem, gptr) \
    asm volatile("cp.async.cg.shared.global [%0], [%1], 16;\n" :: "r"(smem), "l"(gptr))
#define CP_COMMIT() asm volatile("cp.async.commit_group;\n" ::: "memory")
#define CP_WAIT(n)  asm volatile("cp.async.wait_group %0;\n" :: "n"(n) : "memory")

#define LDSM_X4(r, addr) \
    asm volatile("ldmatrix.sync.aligned.m8n8.x4.shared.b16 {%0,%1,%2,%3}, [%4];" \
        : "=r"((r)[0]), "=r"((r)[1]), "=r"((r)[2]), "=r"((r)[3]) : "r"(addr))

#define MMA16816(d, a, b0, b1) \
    asm volatile("mma.sync.aligned.m16n8k16.row.col.f32.f16.f16.f32 " \
        "{%0,%1,%2,%3}, {%4,%5,%6,%7}, {%8,%9}, {%0,%1,%2,%3};" \
        : "+f"((d)[0]), "+f"((d)[1]), "+f"((d)[2]), "+f"((d)[3]) \
        : "r"((a)[0]), "r"((a)[1]), "r"((a)[2]), "r"((a)[3]), "r"(b0), "r"(b1))

// SW128 swizzle for 128B rows, 16B granules
__device__ __forceinline__ uint32_t sw128(int row, int colbyte) {
    return (uint32_t)((row * 128 + colbyte) ^ ((row & 7) << 4));
}

// ---------------------------------------------------------------------------
// fp16 GEMM: C[M,N](f32) = A[M,K](f16, row-major) @ Bt[N,K](f16, K-major)^T
// Grid (N/BN, M/BM), 256 threads, 3-stage cp.async pipeline, ldmatrix + mma.
// ---------------------------------------------------------------------------
__global__ __launch_bounds__(GT, 2)
void gemm_f16(const __half* __restrict__ A, const __half* __restrict__ Bt,
              float* __restrict__ C, int K, int N)
{
    extern __shared__ char smem_raw[];
    const uint32_t base = (smem_u32(smem_raw) + 127u) & ~127u;
    const uint32_t sA = base;
    const uint32_t sB = base + STAGES * STAGE_A;

    const int tid  = threadIdx.x;
    const int wid  = tid >> 5, lane = tid & 31;
    const int mtile = blockIdx.y, ntile = blockIdx.x;
    const int warp_m = wid & 1;        // 2 m-warps (64 rows each)
    const int warp_n = wid >> 1;       // 4 n-warps (32 cols each)

    const __half* Ag = A  + (size_t)(mtile * BM) * K;
    const __half* Bg = Bt + (size_t)(ntile * BN) * K;

    float acc[4][4][4];
    #pragma unroll
    for (int i = 0; i < 4; i++)
        #pragma unroll
        for (int j = 0; j < 4; j++)
            #pragma unroll
            for (int r = 0; r < 4; r++) acc[i][j][r] = 0.f;

    // Stage loader: A and B each 1024 16B-chunks -> 4 chunks/thread each.
    // chunk c -> row = c>>3, col16 = c&7 (128B rows).
    auto load_stage = [&](int s, int k0) {
        uint32_t a0 = sA + s * STAGE_A, b0 = sB + s * STAGE_B;
        #pragma unroll
        for (int j = 0; j < 4; j++) {
            int c = tid + j * 256;
            int r = c >> 3, c16 = c & 7;
            CP_ASYNC16(a0 + sw128(r, c16 * 16), Ag + (size_t)r * K + k0 + c16 * 8);
        }
        #pragma unroll
        for (int j = 0; j < 4; j++) {
            int c = tid + j * 256;
            int r = c >> 3, c16 = c & 7;
            CP_ASYNC16(b0 + sw128(r, c16 * 16), Bg + (size_t)r * K + k0 + c16 * 8);
        }
        CP_COMMIT();
    };

    const int NIT = K / BK;
    load_stage(0, 0);
    load_stage(1, BK);

    int s = 0, s2 = 2;                 // s = compute stage, s2 = prefetch stage
    for (int i = 0; i < NIT; i++) {
        CP_WAIT(1);                    // stage i landed (uniform group accounting)
        __syncthreads();               // all warps done reading buffer s2 (= s-1)
        if (i + 2 < NIT) load_stage(s2, (i + 2) * BK);
        else             CP_COMMIT();  // empty group: keep wait_group arithmetic exact

        const uint32_t aB = sA + s * STAGE_A;
        const uint32_t bB = sB + s * STAGE_B;
        #pragma unroll
        for (int ks = 0; ks < 4; ks++) {
            const int kbyte = ks * 32 + ((lane >> 4) << 4);   // k16 = 32 bytes
            uint32_t a[4][4], bb[2][4];
            #pragma unroll
            for (int ii = 0; ii < 4; ii++) {                  // A: 4 x (m16,k16)
                int row = warp_m * 64 + ii * 16 + (lane & 15);
                LDSM_X4(a[ii], aB + sw128(row, kbyte));
            }
            #pragma unroll
            for (int jj = 0; jj < 2; jj++) {                  // B: 2 x (n16,k16)
                int row = warp_n * 32 + jj * 16 + (lane & 15);
                LDSM_X4(bb[jj], bB + sw128(row, kbyte));
            }
            #pragma unroll
            for (int ii = 0; ii < 4; ii++)
                #pragma unroll
                for (int j = 0; j < 4; j++)
                    MMA16816(acc[ii][j], a[ii], bb[j >> 1][j & 1], bb[j >> 1][2 + (j & 1)]);
        }
        s  = (s  == STAGES - 1) ? 0 : s  + 1;
        s2 = (s2 == STAGES - 1) ? 0 : s2 + 1;
    }

    // Epilogue
    float* Cp = C + (size_t)(mtile * BM) * N + ntile * BN;
    #pragma unroll
    for (int ii = 0; ii < 4; ii++)
        #pragma unroll
        for (int j = 0; j < 4; j++) {
            int r0 = warp_m * 64 + ii * 16 + (lane >> 2);
            int c0 = warp_n * 32 + j * 8 + (lane & 3) * 2;
            float2 v0 = { acc[ii][j][0], acc[ii][j][1] };
            float2 v1 = { acc[ii][j][2], acc[ii][j][3] };
            *(float2*)(Cp + (size_t)r0 * N + c0)       = v0;
            *(float2*)(Cp + (size_t)(r0 + 8) * N + c0) = v1;
        }
}

// ---------------------------------------------------------------------------
// Elementwise fp32 -> fp16 (rn). 4 elems/thread.
// ---------------------------------------------------------------------------
__global__ __launch_bounds__(256)
void f32_to_f16(const float* __restrict__ in, __half* __restrict__ out)
{
    size_t i = (size_t)blockIdx.x * blockDim.x + threadIdx.x;
    float4 v = ((const float4*)in)[i];
    __half2* o = (__half2*)out;
    o[2 * i + 0] = __floats2half2_rn(v.x, v.y);
    o[2 * i + 1] = __floats2half2_rn(v.z, v.w);
}

// ---------------------------------------------------------------------------
// Transpose [R,C] f32 -> [C,R] f16 (rn)
// ---------------------------------------------------------------------------
__global__ __launch_bounds__(256)
void transpose_f16(const float* __restrict__ in, __half* __restrict__ out, int R, int C)
{
    __shared__ float t[32][33];
    const int tx = threadIdx.x, ty = threadIdx.y;     // 32 x 8
    const int bx = blockIdx.x * 32, by = blockIdx.y * 32;
    #pragma unroll
    for (int r = 0; r < 32; r += 8)
        t[ty + r][tx] = in[(size_t)(by + ty + r) * C + bx + tx];
    __syncthreads();
    #pragma unroll
    for (int r = 0; r < 32; r += 8)
        out[(size_t)(bx + ty + r) * R + by + tx] = __float2half_rn(t[tx][ty + r]);
}

// ---------------------------------------------------------------------------
// Per-token attention on the packed qkv buffer (row stride QKV_DIM).
// RoPE cancels exactly in q.k; GQA repeat collapses. Writes ao as fp16.
// ---------------------------------------------------------------------------
__global__ __launch_bounds__(128)
void attn_kernel(const float* __restrict__ qkv, __half* __restrict__ ao)
{
    const int tok = blockIdx.x;
    const int tid = threadIdx.x;

    __shared__ float qs[N_HEADS][132];
    __shared__ float ks[N_KV][132];
    __shared__ float vs[N_KV][132];
    __shared__ float sc[N_HEADS][8];
    __shared__ float w [N_HEADS][8];

    const float* qg = qkv + (size_t)tok * QKV_DIM;
    const float* kg = qg + HS_DIM;
    const float* vg = qg + HS_DIM + KVD_DIM;

    for (int i = tid; i < HS_DIM / 4; i += 128) {
        float4 t4 = *(const float4*)(qg + i * 4);
        int h = (i * 4) >> 7, d = (i * 4) & 127;
        *(float4*)&qs[h][d] = t4;
    }
    for (int i = tid; i < KVD_DIM / 4; i += 128) {
        float4 t4 = *(const float4*)(kg + i * 4);
        int g = (i * 4) >> 7, d = (i * 4) & 127;
        *(float4*)&ks[g][d] = t4;
    }
    for (int i = tid; i < KVD_DIM / 4; i += 128) {
        float4 t4 = *(const float4*)(vg + i * 4);
        int g = (i * 4) >> 7, d = (i * 4) & 127;
        *(float4*)&vs[g][d] = t4;
    }
    __syncthreads();

    const float scale = 0.088388347648318447f;   // 1/sqrt(128)
    #pragma unroll
    for (int r = 0; r < 2; r++) {
        int sid = r * 128 + tid;
        int h = sid >> 3, g = sid & 7;
        float a = 0.f;
        #pragma unroll 8
        for (int d = 0; d < HEAD_D; d++) a += qs[h][d] * ks[g][d];
        sc[h][g] = a * scale;
    }
    __syncthreads();

    if (tid < N_HEADS) {
        float m = sc[tid][0];
        #pragma unroll
        for (int g = 1; g < 8; g++) m = fmaxf(m, sc[tid][g]);
        float e[8], s = 0.f;
        #pragma unroll
        for (int g = 0; g < 8; g++) { e[g] = __expf(sc[tid][g] - m); s += e[g]; }
        float inv = 1.f / s;
        #pragma unroll
        for (int g = 0; g < 8; g++) w[tid][g] = e[g] * inv;
    }
    __syncthreads();

    float vr[8];
    #pragma unroll
    for (int g = 0; g < 8; g++) vr[g] = vs[g][tid];
    __half* og = ao + (size_t)tok * HS_DIM;
    #pragma unroll
    for (int h = 0; h < N_HEADS; h++) {
        float a = 0.f;
        #pragma unroll
        for (int g = 0; g < 8; g++) a += w[h][g] * vr[g];
        og[h * HEAD_D + tid] = __float2half_rn(a);
    }
}

// ---------------------------------------------------------------------------
extern "C" void kernel_launch(void* const* d_in, const int* in_sizes, int n_in,
                              void* d_out, int out_size)
{
    const float* x  = (const float*)d_in[0];
    const float* Wq = (const float*)d_in[1];
    const float* Wk = (const float*)d_in[2];
    const float* Wv = (const float*)d_in[3];
    const float* Wo = (const float*)d_in[4];
    float* out = (float*)d_out;

    float *qkv;
    __half *xh, *aoh, *Wqkv, *WoTh;
    cudaGetSymbolAddress((void**)&qkv,  g_qkv);
    cudaGetSymbolAddress((void**)&xh,   g_xh);
    cudaGetSymbolAddress((void**)&aoh,  g_aoh);
    cudaGetSymbolAddress((void**)&Wqkv, g_Wqkv);
    cudaGetSymbolAddress((void**)&WoTh, g_WoTh);

    cudaFuncSetAttribute(gemm_f16, cudaFuncAttributeMaxDynamicSharedMemorySize, SMEM_BYTES);

    // fp32 -> fp16 input + packed K-major weights (q|k|v rows, then Wo)
    f32_to_f16<<<(size_t)M_TOK * HS_DIM / 1024, 256>>>(x, xh);
    dim3 tb(32, 8);
    transpose_f16<<<dim3(HS_DIM  / 32, HS_DIM / 32), tb>>>(Wq, Wqkv,                        HS_DIM, HS_DIM);
    transpose_f16<<<dim3(KVD_DIM / 32, HS_DIM / 32), tb>>>(Wk, Wqkv + (size_t)HS_DIM * HS_DIM,              HS_DIM, KVD_DIM);
    transpose_f16<<<dim3(KVD_DIM / 32, HS_DIM / 32), tb>>>(Wv, Wqkv + (size_t)(HS_DIM + KVD_DIM) * HS_DIM,  HS_DIM, KVD_DIM);
    transpose_f16<<<dim3(HS_DIM  / 32, HS_DIM / 32), tb>>>(Wo, WoTh, HS_DIM, HS_DIM);

    // Fused q|k|v projection (one GEMM, N = 6144)
    gemm_f16<<<dim3(QKV_DIM / BN, M_TOK / BM), GT, SMEM_BYTES>>>(xh, Wqkv, qkv, HS_DIM, QKV_DIM);

    // Per-token head attention (fp32 in, fp16 out)
    attn_kernel<<<M_TOK, 128>>>(qkv, aoh);

    // Output projection
    gemm_f16<<<dim3(HS_DIM / BN, M_TOK / BM), GT, SMEM_BYTES>>>(aoh, WoTh, out, HS_DIM, HS_DIM);
}